// round 6
// baseline (speedup 1.0000x reference)
#include <cuda_runtime.h>
#include <cuda_fp16.h>
#include <cstdint>

namespace {

constexpr int B_ = 8, H_ = 64, W_ = 64, C_ = 128, N_ = 9, F_ = 256;
constexpr int THREADS = 512;
constexpr int NCHUNK  = N_ * (C_ / 32);   // 36 chunks of K=32
constexpr int PADP    = 20;               // A stride in b32 pairs (16 data + 4 pad)

// dynamic smem layout (b32 units)
constexpr int A_SZ    = 128 * PADP;       // 2560 words per A buffer
constexpr int W_SZ    = 32 * 32 * 4;      // 4096 words per W buffer [ft][lane][ks*2+j]
constexpr int A0_OFF  = 0;
constexpr int A1_OFF  = A_SZ;
constexpr int W0_OFF  = 2 * A_SZ;
constexpr int W1_OFF  = 2 * A_SZ + W_SZ;
constexpr int CRD_OFF = 2 * A_SZ + 2 * W_SZ;
constexpr int SMEM_WORDS = CRD_OFF + 4 * N_ * 128;
constexpr int SMEM_BYTES = SMEM_WORDS * 4;

// Faithful reproduction of reference (2,3,3)->(9,2) reshape order
__constant__ int c_iy[9] = {0, 0, 1, 2, 2, 1, 0, 2, 1};
__constant__ int c_ix[9] = {0, 1, 1, 2, 0, 2, 1, 0, 2};

// fp16 copy of x: [b][y][x][c]
__device__ __half g_xh[B_ * H_ * W_ * C_];
// W fragment image (fp16 pairs): [n][cc][ft(32)][lane(32)][ks(2)][j(2)]
__device__ uint32_t g_Wimg[N_ * 4 * W_SZ];

__device__ __forceinline__ uint32_t pack2(float a, float b) {
    __half2 h = __floats2half2_rn(a, b);
    return *reinterpret_cast<uint32_t*>(&h);
}
__device__ __forceinline__ float2 up2(uint32_t u) {
    return __half22float2(*reinterpret_cast<__half2*>(&u));
}
__device__ __forceinline__ uint32_t smem_u32(const void* p) {
    uint32_t a;
    asm("{ .reg .u64 t; cvta.to.shared.u64 t, %1; cvt.u32.u64 %0, t; }" : "=r"(a) : "l"(p));
    return a;
}
__device__ __forceinline__ void cp_async16(uint32_t dst, const void* src) {
    asm volatile("cp.async.ca.shared.global [%0], [%1], 16;" :: "r"(dst), "l"(src) : "memory");
}
__device__ __forceinline__ void cp_commit() {
    asm volatile("cp.async.commit_group;" ::: "memory");
}
__device__ __forceinline__ void cp_wait0() {
    asm volatile("cp.async.wait_group 0;" ::: "memory");
}
__device__ __forceinline__ void mma_f16(float* c, const uint32_t* a, uint32_t b0, uint32_t b1) {
    asm volatile(
        "mma.sync.aligned.m16n8k16.row.col.f32.f16.f16.f32 "
        "{%0,%1,%2,%3}, {%4,%5,%6,%7}, {%8,%9}, {%0,%1,%2,%3};"
        : "+f"(c[0]), "+f"(c[1]), "+f"(c[2]), "+f"(c[3])
        : "r"(a[0]), "r"(a[1]), "r"(a[2]), "r"(a[3]), "r"(b0), "r"(b1));
}

// lerp 8 channels (4 half2 words) in fp32, repack to half2
__device__ __forceinline__ uint4 lerp8(uint4 lt, uint4 rt, uint4 lb, uint4 rb,
                                       float fy, float fx) {
    uint4 o;
    uint32_t* pl = (uint32_t*)&lt;
    uint32_t* pr = (uint32_t*)&rt;
    uint32_t* ql = (uint32_t*)&lb;
    uint32_t* qr = (uint32_t*)&rb;
    uint32_t* po = (uint32_t*)&o;
    #pragma unroll
    for (int w = 0; w < 4; w++) {
        float2 flt = up2(pl[w]), frt = up2(pr[w]);
        float2 flb = up2(ql[w]), frb = up2(qr[w]);
        float t0 = flt.x + (frt.x - flt.x) * fy;
        float b0 = flb.x + (frb.x - flb.x) * fy;
        float t1 = flt.y + (frt.y - flt.y) * fy;
        float b1 = flb.y + (frb.y - flb.y) * fy;
        po[w] = pack2(t0 + (b0 - t0) * fx, t1 + (b1 - t1) * fx);
    }
    return o;
}

// ---------------- x -> fp16 pre-kernel ----------------
__global__ void xh_kernel(const float* __restrict__ x) {
    int i = (blockIdx.x * 256 + threadIdx.x) * 4;   // 4 floats per thread
    float4 v = *(const float4*)(x + i);
    uint2 o;
    o.x = pack2(v.x, v.y);
    o.y = pack2(v.z, v.w);
    *(uint2*)(g_xh + i) = o;
}

// ---------------- W fragment-image pre-kernel (fp16) ----------------
__global__ void wimg_kernel(const float* __restrict__ Wt) {
    int idx = blockIdx.x * 256 + threadIdx.x;   // 0 .. N_*4*W_SZ-1
    int j    = idx & 1;
    int ks   = (idx >> 1) & 1;
    int lane = (idx >> 2) & 31;
    int ft   = (idx >> 7) & 31;
    int cc   = (idx >> 12) & 3;
    int n    = idx >> 14;
    int gq = lane >> 2, tq = lane & 3;
    int f  = ft * 8 + gq;
    int c0 = cc * 32 + ks * 16 + j * 8 + tq * 2;
    float w0 = Wt[((size_t)n * C_ + c0) * F_ + f];
    float w1 = Wt[((size_t)n * C_ + c0 + 1) * F_ + f];
    g_Wimg[idx] = pack2(w0, w1);
}

// ---------------- main fused kernel ----------------
__global__ __launch_bounds__(THREADS, 1)
void deform_mma_kernel(const float* __restrict__ offs,
                       const float* __restrict__ bias,
                       float* __restrict__ out) {
    extern __shared__ float smf[];
    uint32_t* A_buf[2] = { (uint32_t*)smf + A0_OFF, (uint32_t*)smf + A1_OFF };
    uint32_t* W_buf[2] = { (uint32_t*)smf + W0_OFF, (uint32_t*)smf + W1_OFF };
    int*   s_y0 = (int*)smf + CRD_OFF;
    int*   s_x0 = s_y0 + N_ * 128;
    float* s_fy = (float*)(s_x0 + N_ * 128);
    float* s_fx = s_fy + N_ * 128;

    const uint32_t w_smem_u32[2] = { smem_u32(W_buf[0]), smem_u32(W_buf[1]) };

    const int tid  = threadIdx.x;
    const int wid  = tid >> 5;
    const int lane = tid & 31;
    const int wr   = wid >> 2;        // warp row (0..3): m base = wr*32
    const int wc   = wid & 3;         // warp col (0..3): f base = wc*64
    const int gq   = lane >> 2;
    const int tq   = lane & 3;

    const int blk = blockIdx.x;
    const int b   = blk >> 5;
    const int h0  = (blk & 31) * 2;
    const __half* img = g_xh + (size_t)b * H_ * W_ * C_;

    const int c8  = tid & 3;          // 8-channel slice within 32-ch chunk
    const int pix = tid >> 2;         // 0..127

    // ---- precompute coordinates for all 9 taps ----
    for (int e = tid; e < N_ * 128; e += THREADS) {
        const int n  = e >> 7;
        const int lp = e & 127;
        const int hh = h0 + (lp >> 6);
        const int ww = lp & 63;
        const float* orow = offs + (((size_t)(b * H_ + hh) * W_ + ww) * (2 * N_));
        float cy = (float)(hh - 1 + c_iy[n]) + orow[2 * n];
        float cx = (float)(ww - 1 + c_ix[n]) + orow[2 * n + 1];
        cy = fminf(fmaxf(cy, 0.0f), 63.0f);
        cx = fminf(fmaxf(cx, 0.0f), 63.0f);
        float y0f = floorf(cy);
        float x0f = floorf(cx);
        s_y0[e] = (int)y0f;
        s_x0[e] = (int)x0f;
        s_fy[e] = cy - y0f;
        s_fx[e] = cx - x0f;
    }
    __syncthreads();

    float acc[2][8][4];
    #pragma unroll
    for (int mi = 0; mi < 2; mi++)
        #pragma unroll
        for (int ni = 0; ni < 8; ni++)
            #pragma unroll
            for (int r = 0; r < 4; r++) acc[mi][ni][r] = 0.0f;

    // ---- prologue: stage chunk 0 ----
    {
        const uint32_t* wsrc = g_Wimg;   // n=0, cc=0
        #pragma unroll
        for (int i = 0; i < 2; i++) {
            int o = i * THREADS + tid;
            cp_async16(w_smem_u32[0] + o * 16u, wsrc + o * 4);
        }
        cp_commit();
        const int c_off = c8 * 8;        // cc=0
        const int y0 = s_y0[pix];
        const int x0 = s_x0[pix];
        const int y1 = min(y0 + 1, 63);
        const int x1 = min(x0 + 1, 63);
        uint4 vlt = *(const uint4*)(img + ((y0 * 64 + x0) << 7) + c_off);
        uint4 vrt = *(const uint4*)(img + ((y1 * 64 + x0) << 7) + c_off);
        uint4 vlb = *(const uint4*)(img + ((y0 * 64 + x1) << 7) + c_off);
        uint4 vrb = *(const uint4*)(img + ((y1 * 64 + x1) << 7) + c_off);
        *(uint4*)(A_buf[0] + pix * PADP + c8 * 4) =
            lerp8(vlt, vrt, vlb, vrb, s_fy[pix], s_fx[pix]);
    }

    // ---- main pipelined loop ----
    for (int it = 0; it < NCHUNK; it++) {
        cp_wait0();
        __syncthreads();

        const int buf  = it & 1;
        const int nbuf = buf ^ 1;
        const bool more = (it + 1 < NCHUNK);

        uint4 vlt, vrt, vlb, vrb;
        float pfy, pfx;

        if (more) {
            const int n2  = (it + 1) >> 2;
            const int cc2 = (it + 1) & 3;
            const uint32_t* wsrc = g_Wimg + (size_t)(n2 * 4 + cc2) * W_SZ;
            #pragma unroll
            for (int i = 0; i < 2; i++) {
                int o = i * THREADS + tid;
                cp_async16(w_smem_u32[nbuf] + o * 16u, wsrc + o * 4);
            }
            cp_commit();
            const int c_off = cc2 * 32 + c8 * 8;
            const int e  = n2 * 128 + pix;
            const int y0 = s_y0[e];
            const int x0 = s_x0[e];
            pfy = s_fy[e];
            pfx = s_fx[e];
            const int y1 = min(y0 + 1, 63);
            const int x1 = min(x0 + 1, 63);
            vlt = *(const uint4*)(img + ((y0 * 64 + x0) << 7) + c_off);
            vrt = *(const uint4*)(img + ((y1 * 64 + x0) << 7) + c_off);
            vlb = *(const uint4*)(img + ((y0 * 64 + x1) << 7) + c_off);
            vrb = *(const uint4*)(img + ((y1 * 64 + x1) << 7) + c_off);
        }

        // ---- MMA(it): 2 k-steps of m16n8k16 fp16 ----
        {
            const uint32_t* A_s = A_buf[buf];
            const uint32_t* W_s = W_buf[buf];
            uint32_t a[2][2][4];   // [ks][mi][reg]
            #pragma unroll
            for (int ks = 0; ks < 2; ks++) {
                const int kp = ks * 8 + tq;
                #pragma unroll
                for (int mi = 0; mi < 2; mi++) {
                    const int r0 = wr * 32 + mi * 16 + gq;
                    a[ks][mi][0] = A_s[r0 * PADP + kp];
                    a[ks][mi][1] = A_s[(r0 + 8) * PADP + kp];
                    a[ks][mi][2] = A_s[r0 * PADP + kp + 4];
                    a[ks][mi][3] = A_s[(r0 + 8) * PADP + kp + 4];
                }
            }
            #pragma unroll
            for (int ni = 0; ni < 8; ni++) {
                const int ftl = wc * 8 + ni;
                uint4 bv = *(const uint4*)(W_s + ((ftl * 32) + lane) * 4);
                mma_f16(acc[0][ni], a[0][0], bv.x, bv.y);
                mma_f16(acc[1][ni], a[0][1], bv.x, bv.y);
                mma_f16(acc[0][ni], a[1][0], bv.z, bv.w);
                mma_f16(acc[1][ni], a[1][1], bv.z, bv.w);
            }
        }

        // ---- finish A(it+1): lerp + pack + STS ----
        if (more) {
            *(uint4*)(A_buf[nbuf] + pix * PADP + c8 * 4) =
                lerp8(vlt, vrt, vlb, vrb, pfy, pfx);
        }
    }

    // ---- epilogue: add bias, store ----
    #pragma unroll
    for (int mi = 0; mi < 2; mi++) {
        const int row0 = wr * 32 + mi * 16 + gq;
        float* o0 = out + ((size_t)blk * 128 + row0) * F_;
        float* o1 = o0 + 8 * F_;
        #pragma unroll
        for (int ni = 0; ni < 8; ni++) {
            const int f = wc * 64 + ni * 8 + tq * 2;
            const float2 bb = *(const float2*)(bias + f);
            float2 r0, r1;
            r0.x = acc[mi][ni][0] + bb.x;
            r0.y = acc[mi][ni][1] + bb.y;
            r1.x = acc[mi][ni][2] + bb.x;
            r1.y = acc[mi][ni][3] + bb.y;
            *(float2*)(o0 + f) = r0;
            *(float2*)(o1 + f) = r1;
        }
    }
}

}  // namespace

extern "C" void kernel_launch(void* const* d_in, const int* in_sizes, int n_in,
                              void* d_out, int out_size) {
    (void)in_sizes; (void)n_in; (void)out_size;
    const float* x    = (const float*)d_in[0];   // (8,64,64,128)
    const float* offs = (const float*)d_in[1];   // (8,64,64,18)
    const float* Wt   = (const float*)d_in[2];   // (9,128,256)
    const float* bias = (const float*)d_in[3];   // (256,)
    float* out = (float*)d_out;                  // (8,64,64,256)

    cudaFuncSetAttribute(deform_mma_kernel,
                         cudaFuncAttributeMaxDynamicSharedMemorySize, SMEM_BYTES);

    xh_kernel<<<(B_ * H_ * W_ * C_) / (256 * 4), 256>>>(x);
    wimg_kernel<<<(N_ * 4 * W_SZ) / 256, 256>>>(Wt);
    deform_mma_kernel<<<256, THREADS, SMEM_BYTES>>>(offs, bias, out);
}

// round 7
// speedup vs baseline: 1.0666x; 1.0666x over previous
#include <cuda_runtime.h>
#include <cuda_fp16.h>
#include <cstdint>

namespace {

constexpr int B_ = 8, H_ = 64, W_ = 64, C_ = 128, N_ = 9, F_ = 256;
constexpr int THREADS = 256;
constexpr int NCHUNK  = N_ * (C_ / 32);   // 36 chunks of K=32
constexpr int PADP    = 20;               // A stride in b32 pairs (16 data + 4 pad)

// dynamic smem layout (b32 units)
constexpr int A_SZ    = 64 * PADP;        // 1280 words per A buffer
constexpr int W_SZ    = 32 * 32 * 4;      // 4096 words per W buffer [ft][lane][ks*2+j]
constexpr int A0_OFF  = 0;
constexpr int A1_OFF  = A_SZ;
constexpr int W0_OFF  = 2 * A_SZ;
constexpr int W1_OFF  = 2 * A_SZ + W_SZ;
constexpr int CRD_OFF = 2 * A_SZ + 2 * W_SZ;
constexpr int SMEM_WORDS = CRD_OFF + 4 * N_ * 64;
constexpr int SMEM_BYTES = SMEM_WORDS * 4;    // 52224 B

// Faithful reproduction of reference (2,3,3)->(9,2) reshape order
__constant__ int c_iy[9] = {0, 0, 1, 2, 2, 1, 0, 2, 1};
__constant__ int c_ix[9] = {0, 1, 1, 2, 0, 2, 1, 0, 2};

// fp16 copy of x: [b][y][x][c]
__device__ __half g_xh[B_ * H_ * W_ * C_];
// W fragment image (fp16 pairs): [n][cc][ft(32)][lane(32)][ks(2)][j(2)]
__device__ uint32_t g_Wimg[N_ * 4 * W_SZ];

__device__ __forceinline__ uint32_t pack2(float a, float b) {
    __half2 h = __floats2half2_rn(a, b);
    return *reinterpret_cast<uint32_t*>(&h);
}
__device__ __forceinline__ float2 up2(uint32_t u) {
    return __half22float2(*reinterpret_cast<__half2*>(&u));
}
__device__ __forceinline__ uint32_t smem_u32(const void* p) {
    uint32_t a;
    asm("{ .reg .u64 t; cvta.to.shared.u64 t, %1; cvt.u32.u64 %0, t; }" : "=r"(a) : "l"(p));
    return a;
}
__device__ __forceinline__ void cp_async16(uint32_t dst, const void* src) {
    asm volatile("cp.async.ca.shared.global [%0], [%1], 16;" :: "r"(dst), "l"(src) : "memory");
}
__device__ __forceinline__ void cp_commit() {
    asm volatile("cp.async.commit_group;" ::: "memory");
}
__device__ __forceinline__ void cp_wait0() {
    asm volatile("cp.async.wait_group 0;" ::: "memory");
}
__device__ __forceinline__ void mma_f16(float* c, const uint32_t* a, uint32_t b0, uint32_t b1) {
    asm volatile(
        "mma.sync.aligned.m16n8k16.row.col.f32.f16.f16.f32 "
        "{%0,%1,%2,%3}, {%4,%5,%6,%7}, {%8,%9}, {%0,%1,%2,%3};"
        : "+f"(c[0]), "+f"(c[1]), "+f"(c[2]), "+f"(c[3])
        : "r"(a[0]), "r"(a[1]), "r"(a[2]), "r"(a[3]), "r"(b0), "r"(b1));
}
__device__ __forceinline__ void ldsm_x4(uint32_t* r, uint32_t addr) {
    asm volatile("ldmatrix.sync.aligned.m8n8.x4.shared.b16 {%0,%1,%2,%3}, [%4];"
                 : "=r"(r[0]), "=r"(r[1]), "=r"(r[2]), "=r"(r[3]) : "r"(addr));
}

// lerp 8 channels (4 half2 words) in fp32, repack to half2
__device__ __forceinline__ uint4 lerp8(uint4 lt, uint4 rt, uint4 lb, uint4 rb,
                                       float fy, float fx) {
    uint4 o;
    uint32_t* pl = (uint32_t*)&lt;
    uint32_t* pr = (uint32_t*)&rt;
    uint32_t* ql = (uint32_t*)&lb;
    uint32_t* qr = (uint32_t*)&rb;
    uint32_t* po = (uint32_t*)&o;
    #pragma unroll
    for (int w = 0; w < 4; w++) {
        float2 flt = up2(pl[w]), frt = up2(pr[w]);
        float2 flb = up2(ql[w]), frb = up2(qr[w]);
        float t0 = flt.x + (frt.x - flt.x) * fy;
        float b0 = flb.x + (frb.x - flb.x) * fy;
        float t1 = flt.y + (frt.y - flt.y) * fy;
        float b1 = flb.y + (frb.y - flb.y) * fy;
        po[w] = pack2(t0 + (b0 - t0) * fx, t1 + (b1 - t1) * fx);
    }
    return o;
}

// ---------------- x -> fp16 pre-kernel ----------------
__global__ void xh_kernel(const float* __restrict__ x) {
    int i = (blockIdx.x * 256 + threadIdx.x) * 4;
    float4 v = *(const float4*)(x + i);
    uint2 o;
    o.x = pack2(v.x, v.y);
    o.y = pack2(v.z, v.w);
    *(uint2*)(g_xh + i) = o;
}

// ---------------- W fragment-image pre-kernel (fp16) ----------------
__global__ void wimg_kernel(const float* __restrict__ Wt) {
    int idx = blockIdx.x * 256 + threadIdx.x;   // 0 .. N_*4*W_SZ-1
    int j    = idx & 1;
    int ks   = (idx >> 1) & 1;
    int lane = (idx >> 2) & 31;
    int ft   = (idx >> 7) & 31;
    int cc   = (idx >> 12) & 3;
    int n    = idx >> 14;
    int gq = lane >> 2, tq = lane & 3;
    int f  = ft * 8 + gq;
    int c0 = cc * 32 + ks * 16 + j * 8 + tq * 2;
    float w0 = Wt[((size_t)n * C_ + c0) * F_ + f];
    float w1 = Wt[((size_t)n * C_ + c0 + 1) * F_ + f];
    g_Wimg[idx] = pack2(w0, w1);
}

// ---------------- main fused kernel ----------------
__global__ __launch_bounds__(THREADS, 2)
void deform_mma_kernel(const float* __restrict__ offs,
                       const float* __restrict__ bias,
                       float* __restrict__ out) {
    extern __shared__ float smf[];
    uint32_t* A_buf[2] = { (uint32_t*)smf + A0_OFF, (uint32_t*)smf + A1_OFF };
    uint32_t* W_buf[2] = { (uint32_t*)smf + W0_OFF, (uint32_t*)smf + W1_OFF };
    int*   s_y0 = (int*)smf + CRD_OFF;
    int*   s_x0 = s_y0 + N_ * 64;
    float* s_fy = (float*)(s_x0 + N_ * 64);
    float* s_fx = s_fy + N_ * 64;

    const uint32_t w_smem_u32[2] = { smem_u32(W_buf[0]), smem_u32(W_buf[1]) };
    const uint32_t a_smem_u32[2] = { smem_u32(A_buf[0]), smem_u32(A_buf[1]) };

    const int tid  = threadIdx.x;
    const int wid  = tid >> 5;
    const int lane = tid & 31;
    const int wr   = wid >> 2;        // warp row (0..1): m base = wr*32
    const int wc   = wid & 3;         // warp col (0..3): f base = wc*64
    const int gq   = lane >> 2;
    const int tq   = lane & 3;

    // ldmatrix lane offset within the warp's A block (words)
    const int lrow = (lane & 7) + ((lane >> 3) & 1) * 8;
    const int lcol = (lane >> 4) * 4;
    const uint32_t a_frag_off = (uint32_t)(((wr * 32 + lrow) * PADP + lcol) * 4);

    const int blk = blockIdx.x;       // b*64 + h
    const int b   = blk >> 6;
    const int h   = blk & 63;
    const __half* img = g_xh + (size_t)b * H_ * W_ * C_;

    const int c8  = tid & 3;          // 8-channel slice within 32-ch chunk
    const int pix = tid >> 2;         // 0..63

    // ---- precompute coordinates for all 9 taps (64 pixels each) ----
    for (int e = tid; e < N_ * 64; e += THREADS) {
        const int n  = e >> 6;
        const int ww = e & 63;
        const float* orow = offs + (((size_t)blk * 64 + ww) * (2 * N_));
        float cy = (float)(h - 1 + c_iy[n]) + orow[2 * n];
        float cx = (float)(ww - 1 + c_ix[n]) + orow[2 * n + 1];
        cy = fminf(fmaxf(cy, 0.0f), 63.0f);
        cx = fminf(fmaxf(cx, 0.0f), 63.0f);
        float y0f = floorf(cy);
        float x0f = floorf(cx);
        s_y0[e] = (int)y0f;
        s_x0[e] = (int)x0f;
        s_fy[e] = cy - y0f;
        s_fx[e] = cx - x0f;
    }
    __syncthreads();

    float acc[2][8][4];
    #pragma unroll
    for (int mi = 0; mi < 2; mi++)
        #pragma unroll
        for (int ni = 0; ni < 8; ni++)
            #pragma unroll
            for (int r = 0; r < 4; r++) acc[mi][ni][r] = 0.0f;

    // ---- prologue: stage chunk 0 ----
    {
        const uint32_t* wsrc = g_Wimg;   // n=0, cc=0
        #pragma unroll
        for (int i = 0; i < 4; i++) {
            int o = i * THREADS + tid;
            cp_async16(w_smem_u32[0] + o * 16u, wsrc + o * 4);
        }
        cp_commit();
        const int c_off = c8 * 8;        // cc=0
        const int y0 = s_y0[pix];
        const int x0 = s_x0[pix];
        const int y1 = min(y0 + 1, 63);
        const int x1 = min(x0 + 1, 63);
        uint4 vlt = *(const uint4*)(img + ((y0 * 64 + x0) << 7) + c_off);
        uint4 vrt = *(const uint4*)(img + ((y1 * 64 + x0) << 7) + c_off);
        uint4 vlb = *(const uint4*)(img + ((y0 * 64 + x1) << 7) + c_off);
        uint4 vrb = *(const uint4*)(img + ((y1 * 64 + x1) << 7) + c_off);
        *(uint4*)(A_buf[0] + pix * PADP + c8 * 4) =
            lerp8(vlt, vrt, vlb, vrb, s_fy[pix], s_fx[pix]);
    }

    // ---- main pipelined loop ----
    for (int it = 0; it < NCHUNK; it++) {
        cp_wait0();
        __syncthreads();

        const int buf  = it & 1;
        const int nbuf = buf ^ 1;
        const bool more = (it + 1 < NCHUNK);

        uint4 vlt, vrt, vlb, vrb;
        float pfy, pfx;

        if (more) {
            const int n2  = (it + 1) >> 2;
            const int cc2 = (it + 1) & 3;
            const uint32_t* wsrc = g_Wimg + (size_t)(n2 * 4 + cc2) * W_SZ;
            #pragma unroll
            for (int i = 0; i < 4; i++) {
                int o = i * THREADS + tid;
                cp_async16(w_smem_u32[nbuf] + o * 16u, wsrc + o * 4);
            }
            cp_commit();
            const int c_off = cc2 * 32 + c8 * 8;
            const int e  = n2 * 64 + pix;
            const int y0 = s_y0[e];
            const int x0 = s_x0[e];
            pfy = s_fy[e];
            pfx = s_fx[e];
            const int y1 = min(y0 + 1, 63);
            const int x1 = min(x0 + 1, 63);
            vlt = *(const uint4*)(img + ((y0 * 64 + x0) << 7) + c_off);
            vrt = *(const uint4*)(img + ((y1 * 64 + x0) << 7) + c_off);
            vlb = *(const uint4*)(img + ((y0 * 64 + x1) << 7) + c_off);
            vrb = *(const uint4*)(img + ((y1 * 64 + x1) << 7) + c_off);
        }

        // ---- MMA(it): 2 k-steps of m16n8k16 fp16 ----
        {
            const uint32_t* W_s = W_buf[buf];
            const uint32_t a_base = a_smem_u32[buf] + a_frag_off;
            uint32_t a[2][2][4];   // [ks][mi][reg]
            #pragma unroll
            for (int mi = 0; mi < 2; mi++) {
                ldsm_x4(a[0][mi], a_base + (uint32_t)((mi * 16 * PADP) * 4));
                ldsm_x4(a[1][mi], a_base + (uint32_t)((mi * 16 * PADP + 8) * 4));
            }
            #pragma unroll
            for (int ni = 0; ni < 8; ni++) {
                const int ftl = wc * 8 + ni;
                uint4 bv = *(const uint4*)(W_s + ((ftl * 32) + lane) * 4);
                mma_f16(acc[0][ni], a[0][0], bv.x, bv.y);
                mma_f16(acc[1][ni], a[0][1], bv.x, bv.y);
                mma_f16(acc[0][ni], a[1][0], bv.z, bv.w);
                mma_f16(acc[1][ni], a[1][1], bv.z, bv.w);
            }
        }

        // ---- finish A(it+1): lerp + pack + STS ----
        if (more) {
            *(uint4*)(A_buf[nbuf] + pix * PADP + c8 * 4) =
                lerp8(vlt, vrt, vlb, vrb, pfy, pfx);
        }
    }

    // ---- epilogue: add bias, store ----
    #pragma unroll
    for (int mi = 0; mi < 2; mi++) {
        const int row0 = wr * 32 + mi * 16 + gq;
        float* o0 = out + ((size_t)blk * 64 + row0) * F_;
        float* o1 = o0 + 8 * F_;
        #pragma unroll
        for (int ni = 0; ni < 8; ni++) {
            const int f = wc * 64 + ni * 8 + tq * 2;
            const float2 bb = *(const float2*)(bias + f);
            float2 r0, r1;
            r0.x = acc[mi][ni][0] + bb.x;
            r0.y = acc[mi][ni][1] + bb.y;
            r1.x = acc[mi][ni][2] + bb.x;
            r1.y = acc[mi][ni][3] + bb.y;
            *(float2*)(o0 + f) = r0;
            *(float2*)(o1 + f) = r1;
        }
    }
}

}  // namespace

extern "C" void kernel_launch(void* const* d_in, const int* in_sizes, int n_in,
                              void* d_out, int out_size) {
    (void)in_sizes; (void)n_in; (void)out_size;
    const float* x    = (const float*)d_in[0];   // (8,64,64,128)
    const float* offs = (const float*)d_in[1];   // (8,64,64,18)
    const float* Wt   = (const float*)d_in[2];   // (9,128,256)
    const float* bias = (const float*)d_in[3];   // (256,)
    float* out = (float*)d_out;                  // (8,64,64,256)

    cudaFuncSetAttribute(deform_mma_kernel,
                         cudaFuncAttributeMaxDynamicSharedMemorySize, SMEM_BYTES);

    xh_kernel<<<(B_ * H_ * W_ * C_) / (256 * 4), 256>>>(x);
    wimg_kernel<<<(N_ * 4 * W_SZ) / 256, 256>>>(Wt);
    deform_mma_kernel<<<B_ * H_, THREADS, SMEM_BYTES>>>(offs, bias, out);
}